// round 11
// baseline (speedup 1.0000x reference)
#include <cuda_runtime.h>
#include <cstdint>
#include <cstddef>

// ---------------- problem constants ----------------
static constexpr int NN   = 8192;
static constexpr int NSUP = 3;
static constexpr int DIN  = 32;
static constexpr int DOUT = 32;

// ---------------- tiling ----------------
static constexpr int KT   = 32;               // K per stage
static constexpr int MT   = 64;               // M rows per CTA
static constexpr int NSTG = 12;
static constexpr int STAGES_PER_S = NN / KT;            // 256
static constexpr int T_STAGES     = NSUP * STAGES_PER_S; // 768

static constexpr int ROW_STRIDE = 144;        // 128B data + 16B pad (conflict-free)
static constexpr int A_BYTES = MT * ROW_STRIDE;       // 9216
static constexpr int B_BYTES = DOUT * ROW_STRIDE;     // 4608
static constexpr int STAGE_BYTES = A_BYTES + B_BYTES; // 13824
static constexpr int B_OFF   = A_BYTES;
static constexpr int DYN_BYTES = NSTG * STAGE_BYTES;  // 165888

// scratch: preT[s][o][k] = rna_tf32(x@W[s] + b[s]) transposed
__device__ __align__(256) float g_preT[NSUP * DOUT * NN];

// ---------------- helpers ----------------
__device__ __forceinline__ uint32_t smem_u32(const void* p) {
    uint32_t a;
    asm("{ .reg .u64 t; cvta.to.shared.u64 t, %1; cvt.u32.u64 %0, t; }"
        : "=r"(a) : "l"(p));
    return a;
}
__device__ __forceinline__ void cp_async16(uint32_t dst, const void* src) {
    asm volatile("cp.async.cg.shared.global [%0], [%1], 16;"
                 :: "r"(dst), "l"(src) : "memory");
}
__device__ __forceinline__ void cp_commit() {
    asm volatile("cp.async.commit_group;" ::: "memory");
}
template <int N>
__device__ __forceinline__ void cp_wait() {
    asm volatile("cp.async.wait_group %0;" :: "n"(N) : "memory");
}
__device__ __forceinline__ uint32_t f2tf32(float f) {
    uint32_t u;
    asm("cvt.rna.tf32.f32 %0, %1;" : "=r"(u) : "f"(f));
    return u;
}
__device__ __forceinline__ void mma_tf32(float* c, uint32_t a0, uint32_t a1,
                                         uint32_t a2, uint32_t a3,
                                         uint32_t b0, uint32_t b1) {
    asm volatile(
        "mma.sync.aligned.m16n8k8.row.col.f32.tf32.tf32.f32 "
        "{%0,%1,%2,%3}, {%4,%5,%6,%7}, {%8,%9}, {%0,%1,%2,%3};"
        : "+f"(c[0]), "+f"(c[1]), "+f"(c[2]), "+f"(c[3])
        : "r"(a0), "r"(a1), "r"(a2), "r"(a3), "r"(b0), "r"(b1));
}

// ---------------- precompute: preT[s][o][k] = rna_tf32(x@W + b) ----------------
__global__ void __launch_bounds__(256)
gcn_pre_kernel(const float* __restrict__ x, const float* __restrict__ W,
               const float* __restrict__ b) {
    int idx = blockIdx.x * 256 + threadIdx.x;   // [0, 786432)
    int o = idx & 31;
    int n = (idx >> 5) & (NN - 1);
    int s = idx >> 18;
    const float* xr = x + (size_t)n * DIN;
    const float* wc = W + (size_t)s * DIN * DOUT + o;
    float acc = b[s * DOUT + o];
#pragma unroll
    for (int i = 0; i < DIN; i++)
        acc = fmaf(xr[i], wc[i * DOUT], acc);
    g_preT[((size_t)s * DOUT + o) * NN + n] = __uint_as_float(f2tf32(acc));
}

// ---------------- main: multistage cp.async + mma.sync, 8 warps, K-split ----------------
__global__ void __launch_bounds__(256, 1)
gcn_main_kernel(const float* __restrict__ adj, float* __restrict__ out) {
    extern __shared__ __align__(256) char smem[];
    const uint32_t sb = smem_u32(smem);
    const int tid = threadIdx.x;
    const int m0  = blockIdx.x * MT;

    // ---- per-thread load addressing: A 512 chunks + B 256 chunks over 256 threads ----
    uint32_t a_sm[2]; int a_go[2];
#pragma unroll
    for (int j = 0; j < 2; j++) {
        int id = j * 256 + tid;
        int r = id >> 3, c = id & 7;
        a_sm[j] = (uint32_t)(r * ROW_STRIDE + c * 16);
        a_go[j] = r * NN + c * 4;
    }
    uint32_t b_sm; int b_go;
    {
        int o = tid >> 3, c = tid & 7;
        b_sm = (uint32_t)(B_OFF + o * ROW_STRIDE + c * 16);
        b_go = o * NN + c * 4;
    }

    // ---- per-thread MMA fragment mapping ----
    const int w   = tid >> 5;         // warp 0..7
    const int wm  = w & 3;            // row group: rows 16*wm .. 16*wm+15
    const int j0  = (w >> 2) * 2;     // kstep base: warps 0-3 -> 0,1 ; 4-7 -> 2,3
    const int L   = tid & 31;
    const int g   = L >> 2;
    const int tg  = L & 3;
    const int aoff0 = (wm * 16 + g) * ROW_STRIDE;
    const int aoff1 = aoff0 + 8 * ROW_STRIDE;

    float acc[4][4];
#pragma unroll
    for (int i = 0; i < 4; i++)
#pragma unroll
        for (int j = 0; j < 4; j++) acc[i][j] = 0.0f;

    // ---- stage issue: 3 cp.async per thread ----
    auto issue_stage = [&](int t, int slot) {
        int s  = t >> 8;
        int k0 = (t & 255) << 5;
        uint32_t sbase = sb + slot * STAGE_BYTES;
        const float* aB = adj + (size_t)s * NN * NN + (size_t)m0 * NN + k0;
        const float* bB = g_preT + (size_t)s * DOUT * NN + k0;
#pragma unroll
        for (int j = 0; j < 2; j++) cp_async16(sbase + a_sm[j], aB + a_go[j]);
        cp_async16(sbase + b_sm, bB + b_go);
    };

    // ---- prologue ----
#pragma unroll
    for (int t = 0; t < NSTG - 1; t++) {
        issue_stage(t, t);
        cp_commit();
    }

    // ---- main loop ----
    int slot = 0, pslot = NSTG - 1;
    for (int t = 0; t < T_STAGES; t++) {
        cp_wait<NSTG - 2>();
        __syncthreads();
        if (t + NSTG - 1 < T_STAGES)
            issue_stage(t + NSTG - 1, pslot);
        cp_commit();                   // empty commits in tail keep count aligned
        const char* sB = smem + slot * STAGE_BYTES;
#pragma unroll
        for (int jj = 0; jj < 2; jj++) {     // this warp's 2 ksteps
            int j = j0 + jj;
            const float* r0 = (const float*)(sB + aoff0);
            const float* r1 = (const float*)(sB + aoff1);
            uint32_t a0 = f2tf32(r0[j * 8 + tg]);
            uint32_t a1 = f2tf32(r1[j * 8 + tg]);
            uint32_t a2 = f2tf32(r0[j * 8 + tg + 4]);
            uint32_t a3 = f2tf32(r1[j * 8 + tg + 4]);
#pragma unroll
            for (int nf = 0; nf < 4; nf++) {
                const uint32_t* bp = (const uint32_t*)
                    (sB + B_OFF + (nf * 8 + g) * ROW_STRIDE) + j * 8 + tg;
                mma_tf32(acc[nf], a0, a1, a2, a3, bp[0], bp[4]);
            }
        }
        if (++slot == NSTG)  slot = 0;
        if (++pslot == NSTG) pslot = 0;
    }

    // ---- cross-warp K reduction: warps 4-7 spill, warps 0-3 add ----
    __syncthreads();                   // last stage's smem reads done everywhere
    float* red = (float*)smem;         // reuse slot 0 (8 KB)
    if (w >= 4) {
        float* dst = red + (size_t)(tid - 128) * 16;
#pragma unroll
        for (int nf = 0; nf < 4; nf++)
#pragma unroll
            for (int i = 0; i < 4; i++) dst[nf * 4 + i] = acc[nf][i];
    }
    __syncthreads();
    if (w < 4) {
        const float* src = red + (size_t)tid * 16;
#pragma unroll
        for (int nf = 0; nf < 4; nf++)
#pragma unroll
            for (int i = 0; i < 4; i++) acc[nf][i] += src[nf * 4 + i];

        // ---- epilogue: relu + store ----
        const int mrow = m0 + wm * 16 + g;
        float* o0 = out + (size_t)mrow * DOUT;
        float* o1 = out + (size_t)(mrow + 8) * DOUT;
#pragma unroll
        for (int nf = 0; nf < 4; nf++) {
            int col = nf * 8 + tg * 2;
            o0[col]     = fmaxf(acc[nf][0], 0.0f);
            o0[col + 1] = fmaxf(acc[nf][1], 0.0f);
            o1[col]     = fmaxf(acc[nf][2], 0.0f);
            o1[col + 1] = fmaxf(acc[nf][3], 0.0f);
        }
    }
}

// ---------------- launch ----------------
extern "C" void kernel_launch(void* const* d_in, const int* in_sizes, int n_in,
                              void* d_out, int out_size) {
    const float* x   = (const float*)d_in[0];
    const float* adj = (const float*)d_in[1];
    const float* W   = (const float*)d_in[2];
    const float* b   = (const float*)d_in[3];
    float* out = (float*)d_out;

    cudaFuncSetAttribute(gcn_main_kernel,
                         cudaFuncAttributeMaxDynamicSharedMemorySize, DYN_BYTES);

    gcn_pre_kernel<<<(NSUP * NN * DOUT) / 256, 256>>>(x, W, b);
    gcn_main_kernel<<<NN / MT, 256, DYN_BYTES>>>(adj, out);
}

// round 12
// speedup vs baseline: 1.1090x; 1.1090x over previous
#include <cuda_runtime.h>
#include <cstdint>
#include <cstddef>

// ---------------- problem constants ----------------
static constexpr int NN   = 8192;
static constexpr int NSUP = 3;
static constexpr int DIN  = 32;
static constexpr int DOUT = 32;

// ---------------- tiling ----------------
static constexpr int KT   = 64;               // K per stage (256B rows)
static constexpr int MT   = 64;               // M rows per CTA
static constexpr int NSTG = 6;
static constexpr int STAGES_PER_S = NN / KT;            // 128
static constexpr int T_STAGES     = NSUP * STAGES_PER_S; // 384

static constexpr int ROW_STRIDE = 272;        // 256B data + 16B pad (68 words % 32 == 4)
static constexpr int A_BYTES = MT * ROW_STRIDE;       // 17408
static constexpr int B_BYTES = DOUT * ROW_STRIDE;     // 8704
static constexpr int STAGE_BYTES = A_BYTES + B_BYTES; // 26112
static constexpr int B_OFF   = A_BYTES;
static constexpr int DYN_BYTES = NSTG * STAGE_BYTES;  // 156672

// scratch: preT[s][o][k] = rna_tf32(x@W[s] + b[s]) transposed
__device__ __align__(256) float g_preT[NSUP * DOUT * NN];

// ---------------- helpers ----------------
__device__ __forceinline__ uint32_t smem_u32(const void* p) {
    uint32_t a;
    asm("{ .reg .u64 t; cvta.to.shared.u64 t, %1; cvt.u32.u64 %0, t; }"
        : "=r"(a) : "l"(p));
    return a;
}
__device__ __forceinline__ void cp_async16(uint32_t dst, const void* src) {
    asm volatile("cp.async.cg.shared.global [%0], [%1], 16;"
                 :: "r"(dst), "l"(src) : "memory");
}
__device__ __forceinline__ void cp_commit() {
    asm volatile("cp.async.commit_group;" ::: "memory");
}
template <int N>
__device__ __forceinline__ void cp_wait() {
    asm volatile("cp.async.wait_group %0;" :: "n"(N) : "memory");
}
__device__ __forceinline__ uint32_t f2tf32(float f) {
    uint32_t u;
    asm("cvt.rna.tf32.f32 %0, %1;" : "=r"(u) : "f"(f));
    return u;
}
__device__ __forceinline__ void mma_tf32(float* c, uint32_t a0, uint32_t a1,
                                         uint32_t a2, uint32_t a3,
                                         uint32_t b0, uint32_t b1) {
    asm volatile(
        "mma.sync.aligned.m16n8k8.row.col.f32.tf32.tf32.f32 "
        "{%0,%1,%2,%3}, {%4,%5,%6,%7}, {%8,%9}, {%0,%1,%2,%3};"
        : "+f"(c[0]), "+f"(c[1]), "+f"(c[2]), "+f"(c[3])
        : "r"(a0), "r"(a1), "r"(a2), "r"(a3), "r"(b0), "r"(b1));
}

// ---------------- precompute: preT[s][o][k] = rna_tf32(x@W + b) ----------------
__global__ void __launch_bounds__(256)
gcn_pre_kernel(const float* __restrict__ x, const float* __restrict__ W,
               const float* __restrict__ b) {
    int idx = blockIdx.x * 256 + threadIdx.x;   // [0, 786432)
    int o = idx & 31;
    int n = (idx >> 5) & (NN - 1);
    int s = idx >> 18;
    const float* xr = x + (size_t)n * DIN;
    const float* wc = W + (size_t)s * DIN * DOUT + o;
    float acc = b[s * DOUT + o];
#pragma unroll
    for (int i = 0; i < DIN; i++)
        acc = fmaf(xr[i], wc[i * DOUT], acc);
    g_preT[((size_t)s * DOUT + o) * NN + n] = __uint_as_float(f2tf32(acc));
}

// ---------------- main: multistage cp.async + mma.sync ----------------
// 8 warps: wm in {0,1} owns rows 32*wm..32*wm+31 (2 m-frags, B-frag reuse);
//          kh in {0..3} owns ksteps 2kh, 2kh+1 of the 8 per stage (K-split).
__global__ void __launch_bounds__(256, 1)
gcn_main_kernel(const float* __restrict__ adj, float* __restrict__ out) {
    extern __shared__ __align__(256) char smem[];
    const uint32_t sb = smem_u32(smem);
    const int tid = threadIdx.x;
    const int m0  = blockIdx.x * MT;

    // ---- per-thread load addressing: A 1024 + B 512 chunks of 16B over 256 thr ----
    uint32_t a_sm[4]; int a_go[4];
#pragma unroll
    for (int j = 0; j < 4; j++) {
        int id = j * 256 + tid;
        int r = id >> 4, c = id & 15;
        a_sm[j] = (uint32_t)(r * ROW_STRIDE + c * 16);
        a_go[j] = r * NN + c * 4;
    }
    uint32_t b_sm[2]; int b_go[2];
#pragma unroll
    for (int j = 0; j < 2; j++) {
        int id = j * 256 + tid;
        int o = id >> 4, c = id & 15;
        b_sm[j] = (uint32_t)(B_OFF + o * ROW_STRIDE + c * 16);
        b_go[j] = o * NN + c * 4;
    }

    // ---- per-thread MMA fragment mapping ----
    const int w   = tid >> 5;
    const int wm  = w & 1;            // row half: rows 32*wm..32*wm+31
    const int kh  = w >> 1;           // kstep pair: j = 2*kh + jj
    const int L   = tid & 31;
    const int g   = L >> 2;
    const int tg  = L & 3;
    const int aoff0 = (wm * 32 + g) * ROW_STRIDE;        // mfrag 0 rows g / g+8
    const int aoff1 = aoff0 + 16 * ROW_STRIDE;           // mfrag 1

    float acc[2][4][4];               // [mfrag][nfrag][c]
#pragma unroll
    for (int m = 0; m < 2; m++)
#pragma unroll
        for (int i = 0; i < 4; i++)
#pragma unroll
            for (int j = 0; j < 4; j++) acc[m][i][j] = 0.0f;

    // ---- stage issue: 6 cp.async per thread ----
    auto issue_stage = [&](int t, int slot) {
        int s  = t >> 7;                       // support
        int k0 = (t & 127) << 6;               // K offset
        uint32_t sbase = sb + slot * STAGE_BYTES;
        const float* aB = adj + (size_t)s * NN * NN + (size_t)m0 * NN + k0;
        const float* bB = g_preT + (size_t)s * DOUT * NN + k0;
#pragma unroll
        for (int j = 0; j < 4; j++) cp_async16(sbase + a_sm[j], aB + a_go[j]);
#pragma unroll
        for (int j = 0; j < 2; j++) cp_async16(sbase + b_sm[j], bB + b_go[j]);
    };

    // ---- prologue ----
#pragma unroll
    for (int t = 0; t < NSTG - 1; t++) {
        issue_stage(t, t);
        cp_commit();
    }

    // ---- main loop ----
    int slot = 0, pslot = NSTG - 1;
    for (int t = 0; t < T_STAGES; t++) {
        cp_wait<NSTG - 2>();
        __syncthreads();
        if (t + NSTG - 1 < T_STAGES)
            issue_stage(t + NSTG - 1, pslot);
        cp_commit();                   // empty commits in tail keep count aligned
        const char* sB = smem + slot * STAGE_BYTES;
#pragma unroll
        for (int jj = 0; jj < 2; jj++) {
            const int j = kh * 2 + jj;
            const int kcol = j * 8 + tg;
            const float* r0 = (const float*)(sB + aoff0);
            const float* r1 = (const float*)(sB + aoff0 + 8 * ROW_STRIDE);
            const float* r2 = (const float*)(sB + aoff1);
            const float* r3 = (const float*)(sB + aoff1 + 8 * ROW_STRIDE);
            uint32_t a00 = f2tf32(r0[kcol]);
            uint32_t a01 = f2tf32(r1[kcol]);
            uint32_t a02 = f2tf32(r0[kcol + 4]);
            uint32_t a03 = f2tf32(r1[kcol + 4]);
            uint32_t a10 = f2tf32(r2[kcol]);
            uint32_t a11 = f2tf32(r3[kcol]);
            uint32_t a12 = f2tf32(r2[kcol + 4]);
            uint32_t a13 = f2tf32(r3[kcol + 4]);
#pragma unroll
            for (int nf = 0; nf < 4; nf++) {
                const uint32_t* bp = (const uint32_t*)
                    (sB + B_OFF + (nf * 8 + g) * ROW_STRIDE) + kcol;
                uint32_t b0 = bp[0], b1 = bp[4];
                mma_tf32(acc[0][nf], a00, a01, a02, a03, b0, b1);
                mma_tf32(acc[1][nf], a10, a11, a12, a13, b0, b1);
            }
        }
        if (++slot == NSTG)  slot = 0;
        if (++pslot == NSTG) pslot = 0;
    }

    // ---- 4-way K reduction across kh warps (kh>0 spill, kh==0 adds) ----
    __syncthreads();                   // all stage smem reads done
    float* red = (float*)smem;         // reuse slot 0 (24KB < 26112B)
    if (kh > 0) {
        float* dst = red + ((size_t)((kh - 1) * 2 + wm) * 32 + L) * 32;
#pragma unroll
        for (int m = 0; m < 2; m++)
#pragma unroll
            for (int nf = 0; nf < 4; nf++)
#pragma unroll
                for (int i = 0; i < 4; i++)
                    dst[m * 16 + nf * 4 + i] = acc[m][nf][i];
    }
    __syncthreads();
    if (kh == 0) {
#pragma unroll
        for (int r = 1; r < 4; r++) {
            const float* src = red + ((size_t)((r - 1) * 2 + wm) * 32 + L) * 32;
#pragma unroll
            for (int m = 0; m < 2; m++)
#pragma unroll
                for (int nf = 0; nf < 4; nf++)
#pragma unroll
                    for (int i = 0; i < 4; i++)
                        acc[m][nf][i] += src[m * 16 + nf * 4 + i];
        }
        // ---- epilogue: relu + store ----
#pragma unroll
        for (int m = 0; m < 2; m++) {
            const int mrow = m0 + wm * 32 + m * 16 + g;
            float* o0 = out + (size_t)mrow * DOUT;
            float* o1 = out + (size_t)(mrow + 8) * DOUT;
#pragma unroll
            for (int nf = 0; nf < 4; nf++) {
                int col = nf * 8 + tg * 2;
                o0[col]     = fmaxf(acc[m][nf][0], 0.0f);
                o0[col + 1] = fmaxf(acc[m][nf][1], 0.0f);
                o1[col]     = fmaxf(acc[m][nf][2], 0.0f);
                o1[col + 1] = fmaxf(acc[m][nf][3], 0.0f);
            }
        }
    }
}

// ---------------- launch ----------------
extern "C" void kernel_launch(void* const* d_in, const int* in_sizes, int n_in,
                              void* d_out, int out_size) {
    const float* x   = (const float*)d_in[0];
    const float* adj = (const float*)d_in[1];
    const float* W   = (const float*)d_in[2];
    const float* b   = (const float*)d_in[3];
    float* out = (float*)d_out;

    cudaFuncSetAttribute(gcn_main_kernel,
                         cudaFuncAttributeMaxDynamicSharedMemorySize, DYN_BYTES);

    gcn_pre_kernel<<<(NSUP * NN * DOUT) / 256, 256>>>(x, W, b);
    gcn_main_kernel<<<NN / MT, 256, DYN_BYTES>>>(adj, out);
}

// round 13
// speedup vs baseline: 1.2420x; 1.1199x over previous
#include <cuda_runtime.h>
#include <cstdint>
#include <cstddef>

// ---------------- problem constants ----------------
static constexpr int NN   = 8192;
static constexpr int NSUP = 3;
static constexpr int DIN  = 32;
static constexpr int DOUT = 32;

// ---------------- tiling ----------------
static constexpr int KT   = 64;               // K per stage (256B rows)
static constexpr int MT   = 64;               // M rows per CTA
static constexpr int NSLOT_G = 3;             // slots per group (2 groups)
static constexpr int STAGES_PER_S = NN / KT;            // 128
static constexpr int T_STAGES     = NSUP * STAGES_PER_S; // 384
static constexpr int NI = T_STAGES / 2;       // stages per group = 192

static constexpr int ROW_STRIDE = 272;        // 256B data + 16B pad (68 % 32 == 4)
static constexpr int A_BYTES = MT * ROW_STRIDE;       // 17408
static constexpr int B_BYTES = DOUT * ROW_STRIDE;     // 8704
static constexpr int STAGE_BYTES = A_BYTES + B_BYTES; // 26112
static constexpr int B_OFF   = A_BYTES;
static constexpr int DYN_BYTES = 2 * NSLOT_G * STAGE_BYTES;  // 156672

// scratch: preT[s][o][k] = rna_tf32(x@W[s] + b[s]) transposed
__device__ __align__(256) float g_preT[NSUP * DOUT * NN];

// ---------------- helpers ----------------
__device__ __forceinline__ uint32_t smem_u32(const void* p) {
    uint32_t a;
    asm("{ .reg .u64 t; cvta.to.shared.u64 t, %1; cvt.u32.u64 %0, t; }"
        : "=r"(a) : "l"(p));
    return a;
}
__device__ __forceinline__ void cp_async16(uint32_t dst, const void* src) {
    asm volatile("cp.async.cg.shared.global [%0], [%1], 16;"
                 :: "r"(dst), "l"(src) : "memory");
}
__device__ __forceinline__ void cp_commit() {
    asm volatile("cp.async.commit_group;" ::: "memory");
}
template <int N>
__device__ __forceinline__ void cp_wait() {
    asm volatile("cp.async.wait_group %0;" :: "n"(N) : "memory");
}
__device__ __forceinline__ void group_bar(int id) {
    asm volatile("bar.sync %0, 128;" :: "r"(id) : "memory");
}
__device__ __forceinline__ uint32_t f2tf32(float f) {
    uint32_t u;
    asm("cvt.rna.tf32.f32 %0, %1;" : "=r"(u) : "f"(f));
    return u;
}
__device__ __forceinline__ void mma_tf32(float* c, uint32_t a0, uint32_t a1,
                                         uint32_t a2, uint32_t a3,
                                         uint32_t b0, uint32_t b1) {
    asm volatile(
        "mma.sync.aligned.m16n8k8.row.col.f32.tf32.tf32.f32 "
        "{%0,%1,%2,%3}, {%4,%5,%6,%7}, {%8,%9}, {%0,%1,%2,%3};"
        : "+f"(c[0]), "+f"(c[1]), "+f"(c[2]), "+f"(c[3])
        : "r"(a0), "r"(a1), "r"(a2), "r"(a3), "r"(b0), "r"(b1));
}

// ---------------- precompute: one thread per (s, n), coalesced stores ----------------
__global__ void __launch_bounds__(128)
gcn_pre_kernel(const float* __restrict__ x, const float* __restrict__ W,
               const float* __restrict__ b) {
    __shared__ float Wsh[DIN * DOUT];
    __shared__ float bsh[DOUT];
    const int bx = blockIdx.x;            // 192 blocks = 3 supports x 64
    const int s  = bx >> 6;
    const int n  = ((bx & 63) << 7) + threadIdx.x;

    for (int i = threadIdx.x; i < DIN * DOUT; i += 128)
        Wsh[i] = W[s * DIN * DOUT + i];
    if (threadIdx.x < DOUT) bsh[threadIdx.x] = b[s * DOUT + threadIdx.x];
    __syncthreads();

    float4 xr[DIN / 4];
    const float4* xp = (const float4*)(x + (size_t)n * DIN);
#pragma unroll
    for (int q = 0; q < DIN / 4; q++) xr[q] = xp[q];

    float acc[DOUT];
#pragma unroll
    for (int o = 0; o < DOUT; o++) acc[o] = bsh[o];

    const float4* W4 = (const float4*)Wsh;
    const float* xs = (const float*)xr;
#pragma unroll
    for (int i = 0; i < DIN; i++) {
        float xi = xs[i];
#pragma unroll
        for (int q = 0; q < DOUT / 4; q++) {
            float4 wv = W4[i * (DOUT / 4) + q];
            acc[q * 4 + 0] = fmaf(xi, wv.x, acc[q * 4 + 0]);
            acc[q * 4 + 1] = fmaf(xi, wv.y, acc[q * 4 + 1]);
            acc[q * 4 + 2] = fmaf(xi, wv.z, acc[q * 4 + 2]);
            acc[q * 4 + 3] = fmaf(xi, wv.w, acc[q * 4 + 3]);
        }
    }
#pragma unroll
    for (int o = 0; o < DOUT; o++)   // warp-coalesced: n consecutive across lanes
        g_preT[((size_t)s * DOUT + o) * NN + n] = __uint_as_float(f2tf32(acc[o]));
}

// ---------------- main: two independent 128-thread pipeline groups ----------------
// Group gk (tid>>7) handles stages t = 2i+gk with its own 3 smem slots and its
// own named barrier. Warps: within group, kh = wg&1 (4 ksteps each),
// wm = wg>>1 (32 rows, 2 m-frags). Final 4-way reduction (2 kh x 2 groups).
__global__ void __launch_bounds__(256, 1)
gcn_main_kernel(const float* __restrict__ adj, float* __restrict__ out) {
    extern __shared__ __align__(256) char smem[];
    const uint32_t sb = smem_u32(smem);
    const int tid = threadIdx.x;
    const int m0  = blockIdx.x * MT;
    const int gk  = tid >> 7;             // group 0/1
    const int gt  = tid & 127;            // thread in group
    const uint32_t gbase = sb + (uint32_t)(gk * NSLOT_G) * STAGE_BYTES;

    // ---- per-thread load addressing: A 1024 + B 512 chunks over 128 threads ----
    uint32_t a_sm[8]; int a_go[8];
#pragma unroll
    for (int j = 0; j < 8; j++) {
        int id = j * 128 + gt;
        int r = id >> 4, c = id & 15;
        a_sm[j] = (uint32_t)(r * ROW_STRIDE + c * 16);
        a_go[j] = r * NN + c * 4;
    }
    uint32_t b_sm[4]; int b_go[4];
#pragma unroll
    for (int j = 0; j < 4; j++) {
        int id = j * 128 + gt;
        int o = id >> 4, c = id & 15;
        b_sm[j] = (uint32_t)(B_OFF + o * ROW_STRIDE + c * 16);
        b_go[j] = o * NN + c * 4;
    }

    // ---- MMA fragment mapping ----
    const int wg  = (tid >> 5) & 3;       // warp within group
    const int kh  = wg & 1;               // kstep half: j = kh*4 + jj
    const int wm  = wg >> 1;              // row half: rows 32*wm..32*wm+31
    const int L   = tid & 31;
    const int g   = L >> 2;
    const int tg  = L & 3;
    const int aoff0 = (wm * 32 + g) * ROW_STRIDE;
    const int aoff1 = aoff0 + 16 * ROW_STRIDE;

    float acc[2][4][4];
#pragma unroll
    for (int m = 0; m < 2; m++)
#pragma unroll
        for (int i = 0; i < 4; i++)
#pragma unroll
            for (int j = 0; j < 4; j++) acc[m][i][j] = 0.0f;

    // ---- stage issue: 12 cp.async per thread ----
    auto issue_stage = [&](int i, int slot) {
        int t  = i * 2 + gk;
        int s  = t >> 7;
        int k0 = (t & 127) << 6;
        uint32_t sbase = gbase + (uint32_t)slot * STAGE_BYTES;
        const float* aB = adj + (size_t)s * NN * NN + (size_t)m0 * NN + k0;
        const float* bB = g_preT + (size_t)s * DOUT * NN + k0;
#pragma unroll
        for (int j = 0; j < 8; j++) cp_async16(sbase + a_sm[j], aB + a_go[j]);
#pragma unroll
        for (int j = 0; j < 4; j++) cp_async16(sbase + b_sm[j], bB + b_go[j]);
    };

    // ---- prologue: group stages 0,1 ----
    issue_stage(0, 0); cp_commit();
    issue_stage(1, 1); cp_commit();

    // ---- main loop (independent per group) ----
    int slot = 0, pslot = 2;
    for (int i = 0; i < NI; i++) {
        cp_wait<1>();                     // this thread's stage-i group done
        group_bar(1 + gk);                // whole group's data visible; prior reads done
        if (i + 2 < NI) issue_stage(i + 2, pslot);
        cp_commit();                      // empty commits in tail keep count aligned
        const char* sB = smem + (gk * NSLOT_G + slot) * STAGE_BYTES;
#pragma unroll
        for (int jj = 0; jj < 4; jj++) {
            const int j = kh * 4 + jj;
            const int kcol = j * 8 + tg;
            const float* r0 = (const float*)(sB + aoff0);
            const float* r1 = (const float*)(sB + aoff0 + 8 * ROW_STRIDE);
            const float* r2 = (const float*)(sB + aoff1);
            const float* r3 = (const float*)(sB + aoff1 + 8 * ROW_STRIDE);
            uint32_t a00 = f2tf32(r0[kcol]);
            uint32_t a01 = f2tf32(r1[kcol]);
            uint32_t a02 = f2tf32(r0[kcol + 4]);
            uint32_t a03 = f2tf32(r1[kcol + 4]);
            uint32_t a10 = f2tf32(r2[kcol]);
            uint32_t a11 = f2tf32(r3[kcol]);
            uint32_t a12 = f2tf32(r2[kcol + 4]);
            uint32_t a13 = f2tf32(r3[kcol + 4]);
#pragma unroll
            for (int nf = 0; nf < 4; nf++) {
                const uint32_t* bp = (const uint32_t*)
                    (sB + B_OFF + (nf * 8 + g) * ROW_STRIDE) + kcol;
                uint32_t b0 = bp[0], b1 = bp[4];
                mma_tf32(acc[0][nf], a00, a01, a02, a03, b0, b1);
                mma_tf32(acc[1][nf], a10, a11, a12, a13, b0, b1);
            }
        }
        if (++slot == NSLOT_G)  slot = 0;
        if (++pslot == NSLOT_G) pslot = 0;
    }

    // ---- 4-way reduction: combo c = gk*2+kh; c>0 spill, c==0 adds ----
    __syncthreads();                      // both groups fully done
    const int c = gk * 2 + kh;
    float* red = (float*)smem;            // 24 KB, fits in slot space
    if (c > 0) {
        float* dst = red + (((size_t)(c - 1) * 2 + wm) * 32 + L) * 32;
#pragma unroll
        for (int m = 0; m < 2; m++)
#pragma unroll
            for (int nf = 0; nf < 4; nf++)
#pragma unroll
                for (int i = 0; i < 4; i++)
                    dst[m * 16 + nf * 4 + i] = acc[m][nf][i];
    }
    __syncthreads();
    if (c == 0) {
#pragma unroll
        for (int r = 1; r < 4; r++) {
            const float* src = red + (((size_t)(r - 1) * 2 + wm) * 32 + L) * 32;
#pragma unroll
            for (int m = 0; m < 2; m++)
#pragma unroll
                for (int nf = 0; nf < 4; nf++)
#pragma unroll
                    for (int i = 0; i < 4; i++)
                        acc[m][nf][i] += src[m * 16 + nf * 4 + i];
        }
        // ---- epilogue: relu + store ----
#pragma unroll
        for (int m = 0; m < 2; m++) {
            const int mrow = m0 + wm * 32 + m * 16 + g;
            float* o0 = out + (size_t)mrow * DOUT;
            float* o1 = out + (size_t)(mrow + 8) * DOUT;
#pragma unroll
            for (int nf = 0; nf < 4; nf++) {
                int col = nf * 8 + tg * 2;
                o0[col]     = fmaxf(acc[m][nf][0], 0.0f);
                o0[col + 1] = fmaxf(acc[m][nf][1], 0.0f);
                o1[col]     = fmaxf(acc[m][nf][2], 0.0f);
                o1[col + 1] = fmaxf(acc[m][nf][3], 0.0f);
            }
        }
    }
}

// ---------------- launch ----------------
extern "C" void kernel_launch(void* const* d_in, const int* in_sizes, int n_in,
                              void* d_out, int out_size) {
    const float* x   = (const float*)d_in[0];
    const float* adj = (const float*)d_in[1];
    const float* W   = (const float*)d_in[2];
    const float* b   = (const float*)d_in[3];
    float* out = (float*)d_out;

    cudaFuncSetAttribute(gcn_main_kernel,
                         cudaFuncAttributeMaxDynamicSharedMemorySize, DYN_BYTES);

    gcn_pre_kernel<<<NSUP * (NN / 128), 128>>>(x, W, b);
    gcn_main_kernel<<<NN / MT, 256, DYN_BYTES>>>(adj, out);
}